// round 15
// baseline (speedup 1.0000x reference)
#include <cuda_runtime.h>
#include <cstdint>

#define NN      96
#define GRIDN   9216
#define HIDD    9984
#define OUTD    9600
#define BATCH   256
#define INPD    768
#define KDIM    384
#define HPI     1.5707963267948966f

// Static device scratch for sparse W2.
__device__ int   g_cols[OUTD * 5];
__device__ float g_vals[OUTD * 5];

#define KC     32
#define NCHK   (KDIM / KC)
#define PITCH  40

__device__ __forceinline__ uint32_t f2tf32(float f) {
    uint32_t o;
    asm("cvt.rna.tf32.f32 %0, %1;" : "=r"(o) : "f"(f));
    return o;
}

// ---------------------------------------------------------------------------
// Mega kernel (unchanged from R14 WIN), grid 246:
//   0..143 GEMM | 144..181 build W2 | 182..245 x -> hid tail copy
// ---------------------------------------------------------------------------
__global__ void __launch_bounds__(256)
mega_kernel(const float* __restrict__ X, const float* __restrict__ W1,
            const float* __restrict__ Beta, const float* __restrict__ W2f,
            float* __restrict__ hid) {
    __shared__ uint32_t Xs[128 * PITCH];
    __shared__ uint32_t Ws[128 * PITCH];

    const int b = blockIdx.x;
    const int t = threadIdx.x;

    if (b >= 144) {
        if (b >= 182) {                  // copy role
            int b0 = (b - 182) * 4;
            for (int i = t; i < 4 * 192; i += 256) {
                int bb = b0 + (i / 192);
                int q  = i % 192;
                const float4* src = (const float4*)(X + (size_t)bb * INPD);
                float4*       dst = (float4*)(hid + (size_t)bb * HIDD + GRIDN);
                dst[q] = src[q];
            }
            return;
        }
        int r = (b - 144) * 256 + t;     // build role
        if (r >= OUTD) return;
        const float* Br = Beta + (size_t)r * HIDD;
        const float* Fr = W2f  + (size_t)r * HIDD;
        int c[5]; float v[5];
        if (r < GRIDN) {
            int i = r / NN, j = r % NN;
            c[0] = r; v[0] = Fr[r];
            if (j > 0)      { c[1] = r - 1;              v[1] = Fr[c[1]]; }
            else            { c[1] = GRIDN + 2*NN + i;   v[1] = atanf(Br[c[1]]) + HPI; }
            if (j < NN - 1) { c[2] = r + 1;              v[2] = atanf(Br[c[2]]) + HPI; }
            else            { c[2] = GRIDN + 3*NN + i;   v[2] = atanf(Br[c[2]]) + HPI; }
            if (i > 0)      { c[3] = r - NN;             v[3] = Fr[c[3]]; }
            else            { c[3] = GRIDN + j;          v[3] = atanf(Br[c[3]]) + HPI; }
            if (i < NN - 1) { c[4] = r + NN;             v[4] = atanf(Br[c[4]]) + HPI; }
            else            { c[4] = GRIDN + NN + j;     v[4] = atanf(Br[c[4]]) + HPI; }
        } else {
            int g = r - GRIDN;
            int node;
            if      (g < NN)     node = g;
            else if (g < 2 * NN) node = (NN - 1) * NN + (g - NN);
            else if (g < 3 * NN) node = (g - 2 * NN) * NN;
            else                 node = (g - 3 * NN) * NN + (NN - 1);
            c[0] = r;         v[0] = Fr[r];
            c[1] = node;      v[1] = Fr[node];
            c[2] = OUTD + g;  v[2] = Fr[OUTD + g];
            c[3] = 0;         v[3] = 0.0f;
            c[4] = 0;         v[4] = 0.0f;
        }
#pragma unroll
        for (int k = 0; k < 5; k++) {
            g_cols[r * 5 + k] = c[k];
            g_vals[r * 5 + k] = v[k];
        }
        return;
    }

    // GEMM role
    const int wid  = t >> 5;
    const int lane = t & 31;
    const int g    = lane >> 2;
    const int tg   = lane & 3;
    const int wm   = wid >> 2;
    const int wn   = wid & 3;
    const int m0   = (b / 72) * 128;
    const int n0   = (b % 72) * 128;

    const float* srcp[4];
    uint32_t*    dstp[4];
#pragma unroll
    for (int i = 0; i < 4; i++) {
        int idx  = t + i * 256;
        int tile = idx >> 9;
        int row  = (idx >> 2) & 127;
        int grp  = idx & 3;
        srcp[i] = (tile ? W1 + (size_t)(n0 + row) * INPD
                        : X  + (size_t)(m0 + row) * INPD) + grp * 8;
        dstp[i] = (tile ? Ws : Xs) + row * PITCH + grp * 8;
    }

    float4 lo[4], hi[4];
#pragma unroll
    for (int i = 0; i < 4; i++) {
        lo[i] = *(const float4*)(srcp[i]);
        hi[i] = *(const float4*)(srcp[i] + 4);
    }

    float c[4][4][4];
#pragma unroll
    for (int mf = 0; mf < 4; mf++)
#pragma unroll
        for (int nf = 0; nf < 4; nf++)
#pragma unroll
            for (int q = 0; q < 4; q++) c[mf][nf][q] = 0.0f;

    for (int kc = 0; kc < NCHK; kc++) {
#pragma unroll
        for (int i = 0; i < 4; i++) {
            uint32_t* d = dstp[i];
            d[0] = f2tf32(lo[i].x); d[1] = f2tf32(hi[i].x);
            d[2] = f2tf32(lo[i].y); d[3] = f2tf32(hi[i].y);
            d[4] = f2tf32(lo[i].z); d[5] = f2tf32(hi[i].z);
            d[6] = f2tf32(lo[i].w); d[7] = f2tf32(hi[i].w);
        }
        __syncthreads();

        if (kc + 1 < NCHK) {
            const int off = (kc + 1) * KC;
#pragma unroll
            for (int i = 0; i < 4; i++) {
                lo[i] = *(const float4*)(srcp[i] + off);
                hi[i] = *(const float4*)(srcp[i] + off + 4);
            }
        }

#pragma unroll
        for (int ks = 0; ks < 4; ks++) {
            const int kb = ks * 8 + tg * 2;
            uint2 a0[4], a1[4], bv[4];
#pragma unroll
            for (int mf = 0; mf < 4; mf++) {
                int row = wm * 64 + mf * 16 + g;
                a0[mf] = *(const uint2*)&Xs[row * PITCH + kb];
                a1[mf] = *(const uint2*)&Xs[(row + 8) * PITCH + kb];
            }
#pragma unroll
            for (int nf = 0; nf < 4; nf++) {
                int col = wn * 32 + nf * 8 + g;
                bv[nf] = *(const uint2*)&Ws[col * PITCH + kb];
            }
#pragma unroll
            for (int mf = 0; mf < 4; mf++)
#pragma unroll
                for (int nf = 0; nf < 4; nf++)
                    asm volatile(
                        "mma.sync.aligned.m16n8k8.row.col.f32.tf32.tf32.f32 "
                        "{%0,%1,%2,%3}, {%4,%5,%6,%7}, {%8,%9}, {%0,%1,%2,%3};"
                        : "+f"(c[mf][nf][0]), "+f"(c[mf][nf][1]),
                          "+f"(c[mf][nf][2]), "+f"(c[mf][nf][3])
                        : "r"(a0[mf].x), "r"(a1[mf].x), "r"(a0[mf].y), "r"(a1[mf].y),
                          "r"(bv[nf].x), "r"(bv[nf].y));
        }
        __syncthreads();
    }

#pragma unroll
    for (int mf = 0; mf < 4; mf++) {
        int row = m0 + wm * 64 + mf * 16 + g;
#pragma unroll
        for (int nf = 0; nf < 4; nf++) {
            int col = n0 + wn * 32 + nf * 8 + tg * 2;
            float2* p0 = (float2*)(hid + (size_t)row * HIDD + col);
            float2* p1 = (float2*)(hid + (size_t)(row + 8) * HIDD + col);
            *p0 = make_float2(c[mf][nf][0], c[mf][nf][1]);
            *p1 = make_float2(c[mf][nf][2], c[mf][nf][3]);
        }
    }
}

// ---------------------------------------------------------------------------
// spmm with shared-memory window.
// Grid-row blocks (bx<144): hid[b, r0-96 : r0+160) staged coalesced into smem,
// all 5 taps served from LDS; ghost columns read x directly.
// Ghost-row blocks (144..149): gather path (c0,c2 from x, c1 from hid).
// ---------------------------------------------------------------------------
#define WPITCH 260

__global__ void __launch_bounds__(256)
spmm_kernel(const float* __restrict__ hid, const float* __restrict__ x,
            float* __restrict__ outp) {
    __shared__ int   sc[64 * 5];
    __shared__ float sv[64 * 5];
    __shared__ float W[32 * WPITCH];     // 33280 B window

    const int t   = threadIdx.x;
    const int bx  = blockIdx.x;
    const int r0  = bx * 64;
    const int bb0 = blockIdx.y * 32;

    for (int i = t; i < 320; i += 256) {
        sc[i] = g_cols[r0 * 5 + i];
        sv[i] = g_vals[r0 * 5 + i];
    }

    const int rr = t & 63;
    const int bs = t >> 6;               // 0..3
    const int r  = r0 + rr;

    if (bx < 144) {
        // Stage window: 32 batches x 64 float4 (cols w0 .. w0+255).
        const int w0 = r0 - 96;
        for (int i = t; i < 32 * 64; i += 256) {
            int bi = i >> 6;
            int j  = i & 63;
            int gc = w0 + 4 * j;
            float4 val;
            if (gc >= 0 && gc + 3 < GRIDN) {
                val = *(const float4*)(hid + (size_t)(bb0 + bi) * HIDD + gc);
            } else {
                float e0 = (gc + 0 >= 0 && gc + 0 < GRIDN) ? hid[(size_t)(bb0+bi)*HIDD + gc + 0] : 0.0f;
                float e1 = (gc + 1 >= 0 && gc + 1 < GRIDN) ? hid[(size_t)(bb0+bi)*HIDD + gc + 1] : 0.0f;
                float e2 = (gc + 2 >= 0 && gc + 2 < GRIDN) ? hid[(size_t)(bb0+bi)*HIDD + gc + 2] : 0.0f;
                float e3 = (gc + 3 >= 0 && gc + 3 < GRIDN) ? hid[(size_t)(bb0+bi)*HIDD + gc + 3] : 0.0f;
                val = make_float4(e0, e1, e2, e3);
            }
            *(float4*)&W[bi * WPITCH + 4 * j] = val;
        }
        __syncthreads();

        const int c0 = sc[rr*5+0], c1 = sc[rr*5+1], c2 = sc[rr*5+2],
                  c3 = sc[rr*5+3], c4 = sc[rr*5+4];
        const float v0 = sv[rr*5+0], v1 = sv[rr*5+1], v2 = sv[rr*5+2],
                    v3 = sv[rr*5+3], v4 = sv[rr*5+4];
        // Window offsets (valid when c < GRIDN; ghost taps read x).
        const int o0 = c0 - w0, o1 = c1 - w0, o2 = c2 - w0,
                  o3 = c3 - w0, o4 = c4 - w0;
        const bool g1 = (c1 >= GRIDN), g2 = (c2 >= GRIDN),
                   g3 = (c3 >= GRIDN), g4 = (c4 >= GRIDN);

        float acc[8];
#pragma unroll
        for (int u = 0; u < 8; u++) {
            int bi = bs + 4 * u;
            int b  = bb0 + bi;
            const float* Wb = &W[bi * WPITCH];
            const float* xb = x + (size_t)b * INPD - GRIDN;   // x[c-GRIDN]
            float h0 = Wb[o0];
            float h1 = g1 ? xb[c1] : Wb[o1];
            float h2 = g2 ? xb[c2] : Wb[o2];
            float h3 = g3 ? xb[c3] : Wb[o3];
            float h4 = g4 ? xb[c4] : Wb[o4];
            acc[u] = v0*h0 + v1*h1 + v2*h2 + v3*h3 + v4*h4;
        }
        float* ob = outp + (size_t)(bb0 + bs) * OUTD + r;
#pragma unroll
        for (int u = 0; u < 8; u++) ob[(size_t)u * 4 * OUTD] = acc[u];
        return;
    }

    // Ghost-row blocks (r >= GRIDN): c0 -> x, c1 -> hid gather, c2 -> x.
    __syncthreads();
    const int c0 = sc[rr*5+0], c1 = sc[rr*5+1], c2 = sc[rr*5+2];
    const float v0 = sv[rr*5+0], v1 = sv[rr*5+1], v2 = sv[rr*5+2];

    float acc[8];
#pragma unroll
    for (int u = 0; u < 8; u++) {
        int b = bb0 + bs + 4 * u;
        const float* xb = x + (size_t)b * INPD;
        float h0 = xb[c0 - GRIDN];
        float h1 = hid[(size_t)b * HIDD + c1];
        float h2 = xb[c2 - GRIDN];
        acc[u] = v0*h0 + v1*h1 + v2*h2;
    }
    float* ob = outp + (size_t)(bb0 + bs) * OUTD + r;
#pragma unroll
    for (int u = 0; u < 8; u++) ob[(size_t)u * 4 * OUTD] = acc[u];
}

// ---------------------------------------------------------------------------
extern "C" void kernel_launch(void* const* d_in, const int* in_sizes, int n_in,
                              void* d_out, int out_size) {
    const float* x    = (const float*)d_in[0];
    const float* W1   = (const float*)d_in[1];
    const float* Beta = (const float*)d_in[4];
    const float* W2f  = (const float*)d_in[5];

    if (out_size < BATCH * OUTD + BATCH * HIDD) return;   // layout guard

    float* outp = (float*)d_out;                          // [256, 9600]
    float* hid  = (float*)d_out + (size_t)BATCH * OUTD;   // [256, 9984]

    mega_kernel<<<246, 256>>>(x, W1, Beta, W2f, hid);

    dim3 sgrid(OUTD / 64, 8);             // (150, 8)
    spmm_kernel<<<sgrid, 256>>>(hid, x, outp);
}

// round 16
// speedup vs baseline: 1.2772x; 1.2772x over previous
#include <cuda_runtime.h>
#include <cstdint>

#define NN      96
#define GRIDN   9216
#define HIDD    9984
#define OUTD    9600
#define BATCH   256
#define INPD    768
#define KDIM    384
#define HPI     1.5707963267948966f

// Static device scratch for sparse W2.
__device__ int   g_cols[OUTD * 5];
__device__ float g_vals[OUTD * 5];

#define KC     32
#define NCHK   (KDIM / KC)
#define PITCH  40

__device__ __forceinline__ uint32_t f2tf32(float f) {
    uint32_t o;
    asm("cvt.rna.tf32.f32 %0, %1;" : "=r"(o) : "f"(f));
    return o;
}

// ---------------------------------------------------------------------------
// Mega kernel (unchanged from R14 WIN), grid 246:
//   0..143 GEMM | 144..181 build W2 | 182..245 x -> hid tail copy
// ---------------------------------------------------------------------------
__global__ void __launch_bounds__(256)
mega_kernel(const float* __restrict__ X, const float* __restrict__ W1,
            const float* __restrict__ Beta, const float* __restrict__ W2f,
            float* __restrict__ hid) {
    __shared__ uint32_t Xs[128 * PITCH];
    __shared__ uint32_t Ws[128 * PITCH];

    const int b = blockIdx.x;
    const int t = threadIdx.x;

    if (b >= 144) {
        if (b >= 182) {                  // copy role
            int b0 = (b - 182) * 4;
            for (int i = t; i < 4 * 192; i += 256) {
                int bb = b0 + (i / 192);
                int q  = i % 192;
                const float4* src = (const float4*)(X + (size_t)bb * INPD);
                float4*       dst = (float4*)(hid + (size_t)bb * HIDD + GRIDN);
                dst[q] = src[q];
            }
            return;
        }
        int r = (b - 144) * 256 + t;     // build role
        if (r >= OUTD) return;
        const float* Br = Beta + (size_t)r * HIDD;
        const float* Fr = W2f  + (size_t)r * HIDD;
        int c[5]; float v[5];
        if (r < GRIDN) {
            int i = r / NN, j = r % NN;
            c[0] = r; v[0] = Fr[r];
            if (j > 0)      { c[1] = r - 1;              v[1] = Fr[c[1]]; }
            else            { c[1] = GRIDN + 2*NN + i;   v[1] = atanf(Br[c[1]]) + HPI; }
            if (j < NN - 1) { c[2] = r + 1;              v[2] = atanf(Br[c[2]]) + HPI; }
            else            { c[2] = GRIDN + 3*NN + i;   v[2] = atanf(Br[c[2]]) + HPI; }
            if (i > 0)      { c[3] = r - NN;             v[3] = Fr[c[3]]; }
            else            { c[3] = GRIDN + j;          v[3] = atanf(Br[c[3]]) + HPI; }
            if (i < NN - 1) { c[4] = r + NN;             v[4] = atanf(Br[c[4]]) + HPI; }
            else            { c[4] = GRIDN + NN + j;     v[4] = atanf(Br[c[4]]) + HPI; }
        } else {
            int g = r - GRIDN;
            int node;
            if      (g < NN)     node = g;
            else if (g < 2 * NN) node = (NN - 1) * NN + (g - NN);
            else if (g < 3 * NN) node = (g - 2 * NN) * NN;
            else                 node = (g - 3 * NN) * NN + (NN - 1);
            c[0] = r;         v[0] = Fr[r];
            c[1] = node;      v[1] = Fr[node];
            c[2] = OUTD + g;  v[2] = Fr[OUTD + g];
            c[3] = 0;         v[3] = 0.0f;
            c[4] = 0;         v[4] = 0.0f;
        }
#pragma unroll
        for (int k = 0; k < 5; k++) {
            g_cols[r * 5 + k] = c[k];
            g_vals[r * 5 + k] = v[k];
        }
        return;
    }

    // GEMM role
    const int wid  = t >> 5;
    const int lane = t & 31;
    const int g    = lane >> 2;
    const int tg   = lane & 3;
    const int wm   = wid >> 2;
    const int wn   = wid & 3;
    const int m0   = (b / 72) * 128;
    const int n0   = (b % 72) * 128;

    const float* srcp[4];
    uint32_t*    dstp[4];
#pragma unroll
    for (int i = 0; i < 4; i++) {
        int idx  = t + i * 256;
        int tile = idx >> 9;
        int row  = (idx >> 2) & 127;
        int grp  = idx & 3;
        srcp[i] = (tile ? W1 + (size_t)(n0 + row) * INPD
                        : X  + (size_t)(m0 + row) * INPD) + grp * 8;
        dstp[i] = (tile ? Ws : Xs) + row * PITCH + grp * 8;
    }

    float4 lo[4], hi[4];
#pragma unroll
    for (int i = 0; i < 4; i++) {
        lo[i] = *(const float4*)(srcp[i]);
        hi[i] = *(const float4*)(srcp[i] + 4);
    }

    float c[4][4][4];
#pragma unroll
    for (int mf = 0; mf < 4; mf++)
#pragma unroll
        for (int nf = 0; nf < 4; nf++)
#pragma unroll
            for (int q = 0; q < 4; q++) c[mf][nf][q] = 0.0f;

    for (int kc = 0; kc < NCHK; kc++) {
#pragma unroll
        for (int i = 0; i < 4; i++) {
            uint32_t* d = dstp[i];
            d[0] = f2tf32(lo[i].x); d[1] = f2tf32(hi[i].x);
            d[2] = f2tf32(lo[i].y); d[3] = f2tf32(hi[i].y);
            d[4] = f2tf32(lo[i].z); d[5] = f2tf32(hi[i].z);
            d[6] = f2tf32(lo[i].w); d[7] = f2tf32(hi[i].w);
        }
        __syncthreads();

        if (kc + 1 < NCHK) {
            const int off = (kc + 1) * KC;
#pragma unroll
            for (int i = 0; i < 4; i++) {
                lo[i] = *(const float4*)(srcp[i] + off);
                hi[i] = *(const float4*)(srcp[i] + off + 4);
            }
        }

#pragma unroll
        for (int ks = 0; ks < 4; ks++) {
            const int kb = ks * 8 + tg * 2;
            uint2 a0[4], a1[4], bv[4];
#pragma unroll
            for (int mf = 0; mf < 4; mf++) {
                int row = wm * 64 + mf * 16 + g;
                a0[mf] = *(const uint2*)&Xs[row * PITCH + kb];
                a1[mf] = *(const uint2*)&Xs[(row + 8) * PITCH + kb];
            }
#pragma unroll
            for (int nf = 0; nf < 4; nf++) {
                int col = wn * 32 + nf * 8 + g;
                bv[nf] = *(const uint2*)&Ws[col * PITCH + kb];
            }
#pragma unroll
            for (int mf = 0; mf < 4; mf++)
#pragma unroll
                for (int nf = 0; nf < 4; nf++)
                    asm volatile(
                        "mma.sync.aligned.m16n8k8.row.col.f32.tf32.tf32.f32 "
                        "{%0,%1,%2,%3}, {%4,%5,%6,%7}, {%8,%9}, {%0,%1,%2,%3};"
                        : "+f"(c[mf][nf][0]), "+f"(c[mf][nf][1]),
                          "+f"(c[mf][nf][2]), "+f"(c[mf][nf][3])
                        : "r"(a0[mf].x), "r"(a1[mf].x), "r"(a0[mf].y), "r"(a1[mf].y),
                          "r"(bv[nf].x), "r"(bv[nf].y));
        }
        __syncthreads();
    }

#pragma unroll
    for (int mf = 0; mf < 4; mf++) {
        int row = m0 + wm * 64 + mf * 16 + g;
#pragma unroll
        for (int nf = 0; nf < 4; nf++) {
            int col = n0 + wn * 32 + nf * 8 + tg * 2;
            float2* p0 = (float2*)(hid + (size_t)row * HIDD + col);
            float2* p1 = (float2*)(hid + (size_t)(row + 8) * HIDD + col);
            *p0 = make_float2(c[mf][nf][0], c[mf][nf][1]);
            *p1 = make_float2(c[mf][nf][2], c[mf][nf][3]);
        }
    }
}

// ---------------------------------------------------------------------------
// spmm v2: 4-row vectorized taps.
// Grid-row blocks (bx<144): thread = (row-group of 4, batch lane); per batch
// 5 vector loads serve 20 taps; float4 output stores. Ghost taps read x.
// Ghost-row blocks (144..149): 3-tap path (diag/ident from x, node from hid).
// ---------------------------------------------------------------------------
__global__ void __launch_bounds__(256)
spmm_kernel(const float* __restrict__ hid, const float* __restrict__ x,
            float* __restrict__ outp) {
    const int t   = threadIdx.x;
    const int bx  = blockIdx.x;
    const int r0  = bx * 64;
    const int bb0 = blockIdx.y * 32;

    if (bx < 144) {
        const int rg = t & 15;           // row group 0..15
        const int bs = t >> 4;           // batch lane 0..15
        const int r4 = r0 + rg * 4;
        const int i  = r4 / NN;
        const int j0 = r4 % NN;          // multiple of 4, group stays in row i
        const bool topg = (i == 0), botg = (i == NN - 1);
        const bool lg   = (j0 == 0), rgh = (j0 == NN - 4);

        // 20 values for the 4 rows (slot order: diag,left,right,up,down).
        float v[20];
#pragma unroll
        for (int q = 0; q < 5; q++)
            *(float4*)&v[q * 4] = *(const float4*)&g_vals[r4 * 5 + q * 4];

#pragma unroll
        for (int u = 0; u < 2; u++) {
            const int b = bb0 + bs + 16 * u;
            const float* hb = hid + (size_t)b * HIDD;
            const float* xb = x   + (size_t)b * INPD;

            float4 ctr = *(const float4*)&hb[r4];
            float  lft = lg   ? xb[2 * NN + i] : hb[r4 - 1];
            float  rgt = rgh  ? xb[3 * NN + i] : hb[r4 + 4];
            float4 up  = topg ? *(const float4*)&xb[j0]
                              : *(const float4*)&hb[r4 - NN];
            float4 dn  = botg ? *(const float4*)&xb[NN + j0]
                              : *(const float4*)&hb[r4 + NN];

            float4 o;
            o.x = v[0]*ctr.x  + v[1]*lft    + v[2]*ctr.y  + v[3]*up.x  + v[4]*dn.x;
            o.y = v[5]*ctr.y  + v[6]*ctr.x  + v[7]*ctr.z  + v[8]*up.y  + v[9]*dn.y;
            o.z = v[10]*ctr.z + v[11]*ctr.y + v[12]*ctr.w + v[13]*up.z + v[14]*dn.z;
            o.w = v[15]*ctr.w + v[16]*ctr.z + v[17]*rgt   + v[18]*up.w + v[19]*dn.w;
            *(float4*)&outp[(size_t)b * OUTD + r4] = o;
        }
        return;
    }

    // Ghost-row blocks: r in [9216, 9600); taps: diag->x, node->hid, ident->x.
    const int rr = t & 63;
    const int bs = t >> 6;               // 0..3
    const int r  = r0 + rr;
    const int gg = r - GRIDN;
    int node;
    if      (gg < NN)     node = gg;
    else if (gg < 2 * NN) node = (NN - 1) * NN + (gg - NN);
    else if (gg < 3 * NN) node = (gg - 2 * NN) * NN;
    else                  node = (gg - 3 * NN) * NN + (NN - 1);

    const float v0 = g_vals[r * 5 + 0];
    const float v1 = g_vals[r * 5 + 1];
    const float v2 = g_vals[r * 5 + 2];

#pragma unroll
    for (int u = 0; u < 8; u++) {
        int b = bb0 + bs + 4 * u;
        const float* xb = x + (size_t)b * INPD;
        float h0 = xb[gg];                              // col r -> x[r-GRIDN]
        float h1 = hid[(size_t)b * HIDD + node];        // grid node
        float h2 = xb[4 * NN + gg];                     // identity col
        outp[(size_t)b * OUTD + r] = v0 * h0 + v1 * h1 + v2 * h2;
    }
}

// ---------------------------------------------------------------------------
extern "C" void kernel_launch(void* const* d_in, const int* in_sizes, int n_in,
                              void* d_out, int out_size) {
    const float* x    = (const float*)d_in[0];
    const float* W1   = (const float*)d_in[1];
    const float* Beta = (const float*)d_in[4];
    const float* W2f  = (const float*)d_in[5];

    if (out_size < BATCH * OUTD + BATCH * HIDD) return;   // layout guard

    float* outp = (float*)d_out;                          // [256, 9600]
    float* hid  = (float*)d_out + (size_t)BATCH * OUTD;   // [256, 9984]

    mega_kernel<<<246, 256>>>(x, W1, Beta, W2f, hid);

    dim3 sgrid(OUTD / 64, 8);             // (150, 8)
    spmm_kernel<<<sgrid, 256>>>(hid, x, outp);
}

// round 17
// speedup vs baseline: 1.2786x; 1.0011x over previous
#include <cuda_runtime.h>
#include <cstdint>

#define NN      96
#define GRIDN   9216
#define HIDD    9984
#define OUTD    9600
#define BATCH   256
#define INPD    768
#define KDIM    384
#define HPI     1.5707963267948966f

// Static device scratch for sparse W2.
__device__ int   g_cols[OUTD * 5];
__device__ float g_vals[OUTD * 5];

#define KC     32
#define NCHK   (KDIM / KC)
#define PITCH  40

__device__ __forceinline__ uint32_t f2tf32(float f) {
    uint32_t o;
    asm("cvt.rna.tf32.f32 %0, %1;" : "=r"(o) : "f"(f));
    return o;
}

// ---------------------------------------------------------------------------
// Mega kernel (unchanged from R14 WIN), grid 246:
//   0..143 GEMM | 144..181 build W2 | 182..245 x -> hid tail copy
// ---------------------------------------------------------------------------
__global__ void __launch_bounds__(256)
mega_kernel(const float* __restrict__ X, const float* __restrict__ W1,
            const float* __restrict__ Beta, const float* __restrict__ W2f,
            float* __restrict__ hid) {
    __shared__ uint32_t Xs[128 * PITCH];
    __shared__ uint32_t Ws[128 * PITCH];

    const int b = blockIdx.x;
    const int t = threadIdx.x;

    if (b >= 144) {
        if (b >= 182) {                  // copy role
            int b0 = (b - 182) * 4;
            for (int i = t; i < 4 * 192; i += 256) {
                int bb = b0 + (i / 192);
                int q  = i % 192;
                const float4* src = (const float4*)(X + (size_t)bb * INPD);
                float4*       dst = (float4*)(hid + (size_t)bb * HIDD + GRIDN);
                dst[q] = src[q];
            }
            return;
        }
        int r = (b - 144) * 256 + t;     // build role
        if (r >= OUTD) return;
        const float* Br = Beta + (size_t)r * HIDD;
        const float* Fr = W2f  + (size_t)r * HIDD;
        int c[5]; float v[5];
        if (r < GRIDN) {
            int i = r / NN, j = r % NN;
            c[0] = r; v[0] = Fr[r];
            if (j > 0)      { c[1] = r - 1;              v[1] = Fr[c[1]]; }
            else            { c[1] = GRIDN + 2*NN + i;   v[1] = atanf(Br[c[1]]) + HPI; }
            if (j < NN - 1) { c[2] = r + 1;              v[2] = atanf(Br[c[2]]) + HPI; }
            else            { c[2] = GRIDN + 3*NN + i;   v[2] = atanf(Br[c[2]]) + HPI; }
            if (i > 0)      { c[3] = r - NN;             v[3] = Fr[c[3]]; }
            else            { c[3] = GRIDN + j;          v[3] = atanf(Br[c[3]]) + HPI; }
            if (i < NN - 1) { c[4] = r + NN;             v[4] = atanf(Br[c[4]]) + HPI; }
            else            { c[4] = GRIDN + NN + j;     v[4] = atanf(Br[c[4]]) + HPI; }
        } else {
            int g = r - GRIDN;
            int node;
            if      (g < NN)     node = g;
            else if (g < 2 * NN) node = (NN - 1) * NN + (g - NN);
            else if (g < 3 * NN) node = (g - 2 * NN) * NN;
            else                 node = (g - 3 * NN) * NN + (NN - 1);
            c[0] = r;         v[0] = Fr[r];
            c[1] = node;      v[1] = Fr[node];
            c[2] = OUTD + g;  v[2] = Fr[OUTD + g];
            c[3] = 0;         v[3] = 0.0f;
            c[4] = 0;         v[4] = 0.0f;
        }
#pragma unroll
        for (int k = 0; k < 5; k++) {
            g_cols[r * 5 + k] = c[k];
            g_vals[r * 5 + k] = v[k];
        }
        return;
    }

    // GEMM role
    const int wid  = t >> 5;
    const int lane = t & 31;
    const int g    = lane >> 2;
    const int tg   = lane & 3;
    const int wm   = wid >> 2;
    const int wn   = wid & 3;
    const int m0   = (b / 72) * 128;
    const int n0   = (b % 72) * 128;

    const float* srcp[4];
    uint32_t*    dstp[4];
#pragma unroll
    for (int i = 0; i < 4; i++) {
        int idx  = t + i * 256;
        int tile = idx >> 9;
        int row  = (idx >> 2) & 127;
        int grp  = idx & 3;
        srcp[i] = (tile ? W1 + (size_t)(n0 + row) * INPD
                        : X  + (size_t)(m0 + row) * INPD) + grp * 8;
        dstp[i] = (tile ? Ws : Xs) + row * PITCH + grp * 8;
    }

    float4 lo[4], hi[4];
#pragma unroll
    for (int i = 0; i < 4; i++) {
        lo[i] = *(const float4*)(srcp[i]);
        hi[i] = *(const float4*)(srcp[i] + 4);
    }

    float c[4][4][4];
#pragma unroll
    for (int mf = 0; mf < 4; mf++)
#pragma unroll
        for (int nf = 0; nf < 4; nf++)
#pragma unroll
            for (int q = 0; q < 4; q++) c[mf][nf][q] = 0.0f;

    for (int kc = 0; kc < NCHK; kc++) {
#pragma unroll
        for (int i = 0; i < 4; i++) {
            uint32_t* d = dstp[i];
            d[0] = f2tf32(lo[i].x); d[1] = f2tf32(hi[i].x);
            d[2] = f2tf32(lo[i].y); d[3] = f2tf32(hi[i].y);
            d[4] = f2tf32(lo[i].z); d[5] = f2tf32(hi[i].z);
            d[6] = f2tf32(lo[i].w); d[7] = f2tf32(hi[i].w);
        }
        __syncthreads();

        if (kc + 1 < NCHK) {
            const int off = (kc + 1) * KC;
#pragma unroll
            for (int i = 0; i < 4; i++) {
                lo[i] = *(const float4*)(srcp[i] + off);
                hi[i] = *(const float4*)(srcp[i] + off + 4);
            }
        }

#pragma unroll
        for (int ks = 0; ks < 4; ks++) {
            const int kb = ks * 8 + tg * 2;
            uint2 a0[4], a1[4], bv[4];
#pragma unroll
            for (int mf = 0; mf < 4; mf++) {
                int row = wm * 64 + mf * 16 + g;
                a0[mf] = *(const uint2*)&Xs[row * PITCH + kb];
                a1[mf] = *(const uint2*)&Xs[(row + 8) * PITCH + kb];
            }
#pragma unroll
            for (int nf = 0; nf < 4; nf++) {
                int col = wn * 32 + nf * 8 + g;
                bv[nf] = *(const uint2*)&Ws[col * PITCH + kb];
            }
#pragma unroll
            for (int mf = 0; mf < 4; mf++)
#pragma unroll
                for (int nf = 0; nf < 4; nf++)
                    asm volatile(
                        "mma.sync.aligned.m16n8k8.row.col.f32.tf32.tf32.f32 "
                        "{%0,%1,%2,%3}, {%4,%5,%6,%7}, {%8,%9}, {%0,%1,%2,%3};"
                        : "+f"(c[mf][nf][0]), "+f"(c[mf][nf][1]),
                          "+f"(c[mf][nf][2]), "+f"(c[mf][nf][3])
                        : "r"(a0[mf].x), "r"(a1[mf].x), "r"(a0[mf].y), "r"(a1[mf].y),
                          "r"(bv[nf].x), "r"(bv[nf].y));
        }
        __syncthreads();
    }

#pragma unroll
    for (int mf = 0; mf < 4; mf++) {
        int row = m0 + wm * 64 + mf * 16 + g;
#pragma unroll
        for (int nf = 0; nf < 4; nf++) {
            int col = n0 + wn * 32 + nf * 8 + tg * 2;
            float2* p0 = (float2*)(hid + (size_t)row * HIDD + col);
            float2* p1 = (float2*)(hid + (size_t)(row + 8) * HIDD + col);
            *p0 = make_float2(c[mf][nf][0], c[mf][nf][1]);
            *p1 = make_float2(c[mf][nf][2], c[mf][nf][3]);
        }
    }
}

// ---------------------------------------------------------------------------
// spmm v2: 4-row vectorized taps.
// Grid-row blocks (bx<144): thread = (row-group of 4, batch lane); per batch
// 5 vector loads serve 20 taps; float4 output stores. Ghost taps read x.
// Ghost-row blocks (144..149): 3-tap path (diag/ident from x, node from hid).
// ---------------------------------------------------------------------------
__global__ void __launch_bounds__(256)
spmm_kernel(const float* __restrict__ hid, const float* __restrict__ x,
            float* __restrict__ outp) {
    const int t   = threadIdx.x;
    const int bx  = blockIdx.x;
    const int r0  = bx * 64;
    const int bb0 = blockIdx.y * 32;

    if (bx < 144) {
        const int rg = t & 15;           // row group 0..15
        const int bs = t >> 4;           // batch lane 0..15
        const int r4 = r0 + rg * 4;
        const int i  = r4 / NN;
        const int j0 = r4 % NN;          // multiple of 4, group stays in row i
        const bool topg = (i == 0), botg = (i == NN - 1);
        const bool lg   = (j0 == 0), rgh = (j0 == NN - 4);

        // 20 values for the 4 rows (slot order: diag,left,right,up,down).
        float v[20];
#pragma unroll
        for (int q = 0; q < 5; q++)
            *(float4*)&v[q * 4] = *(const float4*)&g_vals[r4 * 5 + q * 4];

#pragma unroll
        for (int u = 0; u < 2; u++) {
            const int b = bb0 + bs + 16 * u;
            const float* hb = hid + (size_t)b * HIDD;
            const float* xb = x   + (size_t)b * INPD;

            float4 ctr = *(const float4*)&hb[r4];
            float  lft = lg   ? xb[2 * NN + i] : hb[r4 - 1];
            float  rgt = rgh  ? xb[3 * NN + i] : hb[r4 + 4];
            float4 up  = topg ? *(const float4*)&xb[j0]
                              : *(const float4*)&hb[r4 - NN];
            float4 dn  = botg ? *(const float4*)&xb[NN + j0]
                              : *(const float4*)&hb[r4 + NN];

            float4 o;
            o.x = v[0]*ctr.x  + v[1]*lft    + v[2]*ctr.y  + v[3]*up.x  + v[4]*dn.x;
            o.y = v[5]*ctr.y  + v[6]*ctr.x  + v[7]*ctr.z  + v[8]*up.y  + v[9]*dn.y;
            o.z = v[10]*ctr.z + v[11]*ctr.y + v[12]*ctr.w + v[13]*up.z + v[14]*dn.z;
            o.w = v[15]*ctr.w + v[16]*ctr.z + v[17]*rgt   + v[18]*up.w + v[19]*dn.w;
            *(float4*)&outp[(size_t)b * OUTD + r4] = o;
        }
        return;
    }

    // Ghost-row blocks: r in [9216, 9600); taps: diag->x, node->hid, ident->x.
    const int rr = t & 63;
    const int bs = t >> 6;               // 0..3
    const int r  = r0 + rr;
    const int gg = r - GRIDN;
    int node;
    if      (gg < NN)     node = gg;
    else if (gg < 2 * NN) node = (NN - 1) * NN + (gg - NN);
    else if (gg < 3 * NN) node = (gg - 2 * NN) * NN;
    else                  node = (gg - 3 * NN) * NN + (NN - 1);

    const float v0 = g_vals[r * 5 + 0];
    const float v1 = g_vals[r * 5 + 1];
    const float v2 = g_vals[r * 5 + 2];

#pragma unroll
    for (int u = 0; u < 8; u++) {
        int b = bb0 + bs + 4 * u;
        const float* xb = x + (size_t)b * INPD;
        float h0 = xb[gg];                              // col r -> x[r-GRIDN]
        float h1 = hid[(size_t)b * HIDD + node];        // grid node
        float h2 = xb[4 * NN + gg];                     // identity col
        outp[(size_t)b * OUTD + r] = v0 * h0 + v1 * h1 + v2 * h2;
    }
}

// ---------------------------------------------------------------------------
extern "C" void kernel_launch(void* const* d_in, const int* in_sizes, int n_in,
                              void* d_out, int out_size) {
    const float* x    = (const float*)d_in[0];
    const float* W1   = (const float*)d_in[1];
    const float* Beta = (const float*)d_in[4];
    const float* W2f  = (const float*)d_in[5];

    if (out_size < BATCH * OUTD + BATCH * HIDD) return;   // layout guard

    float* outp = (float*)d_out;                          // [256, 9600]
    float* hid  = (float*)d_out + (size_t)BATCH * OUTD;   // [256, 9984]

    mega_kernel<<<246, 256>>>(x, W1, Beta, W2f, hid);

    dim3 sgrid(OUTD / 64, 8);             // (150, 8)
    spmm_kernel<<<sgrid, 256>>>(hid, x, outp);
}